// round 1
// baseline (speedup 1.0000x reference)
#include <cuda_runtime.h>

#define TT 512
#define BB 32
#define II 1024
#define HH 1024
#define G4 4096   // 4*H

// 256 MB scratch for gates_pre [T][B][4H]
__device__ float g_gates[(size_t)TT * BB * G4];

// ----------------------------------------------------------------------------
// GEMM1: g_gates[m][n] = sum_k x[m][k] * W[n][k] + bW[n] + bR[n]
// M = T*B = 16384, N = 4096, K = 1024. NT layout (both K-major).
// Tile: BM=128, BN=64, BK=16. 256 threads, 8x4 microtile.
// ----------------------------------------------------------------------------
__global__ __launch_bounds__(256) void gemm_pre(const float* __restrict__ x,
                                                const float* __restrict__ W,
                                                const float* __restrict__ bW,
                                                const float* __restrict__ bR)
{
    __shared__ float AsT[16][132];   // [k][m], padded rows (528B, 16B aligned)
    __shared__ float BsT[16][68];    // [k][n], padded rows (272B, 16B aligned)

    const int tid = threadIdx.x;
    const int n0 = blockIdx.x * 64;
    const int m0 = blockIdx.y * 128;
    const int tx = tid & 15;     // 16 cols of 4 -> 64 n
    const int ty = tid >> 4;     // 16 rows of 8 -> 128 m

    float acc[8][4];
#pragma unroll
    for (int i = 0; i < 8; i++)
#pragma unroll
        for (int j = 0; j < 4; j++) acc[i][j] = 0.f;

    for (int k0 = 0; k0 < II; k0 += 16) {
        // Load A tile 128x16 (transposed into smem)
#pragma unroll
        for (int q = 0; q < 2; q++) {
            int f   = tid * 2 + q;          // 0..511
            int row = f >> 2;               // 0..127
            int c4  = (f & 3) * 4;          // 0,4,8,12
            float4 v = *(const float4*)&x[(size_t)(m0 + row) * II + k0 + c4];
            AsT[c4 + 0][row] = v.x;
            AsT[c4 + 1][row] = v.y;
            AsT[c4 + 2][row] = v.z;
            AsT[c4 + 3][row] = v.w;
        }
        // Load B (=W) tile 64x16 (transposed into smem)
        {
            int row = tid >> 2;             // 0..63
            int c4  = (tid & 3) * 4;
            float4 v = *(const float4*)&W[(size_t)(n0 + row) * II + k0 + c4];
            BsT[c4 + 0][row] = v.x;
            BsT[c4 + 1][row] = v.y;
            BsT[c4 + 2][row] = v.z;
            BsT[c4 + 3][row] = v.w;
        }
        __syncthreads();

#pragma unroll
        for (int k = 0; k < 16; k++) {
            float4 a0 = *(const float4*)&AsT[k][ty * 8];
            float4 a1 = *(const float4*)&AsT[k][ty * 8 + 4];
            float4 bv = *(const float4*)&BsT[k][tx * 4];
            float a[8] = {a0.x, a0.y, a0.z, a0.w, a1.x, a1.y, a1.z, a1.w};
            float b[4] = {bv.x, bv.y, bv.z, bv.w};
#pragma unroll
            for (int i = 0; i < 8; i++)
#pragma unroll
                for (int j = 0; j < 4; j++)
                    acc[i][j] += a[i] * b[j];
        }
        __syncthreads();
    }

    // Epilogue: add bias, write gates_pre
    float bias[4];
#pragma unroll
    for (int j = 0; j < 4; j++) {
        int n = n0 + tx * 4 + j;
        bias[j] = bW[n] + bR[n];
    }
#pragma unroll
    for (int i = 0; i < 8; i++) {
        int m = m0 + ty * 8 + i;
        float* outp = &g_gates[(size_t)m * G4 + n0 + tx * 4];
#pragma unroll
        for (int j = 0; j < 4; j++)
            outp[j] = acc[i][j] + bias[j];
    }
}

// ----------------------------------------------------------------------------
// One recurrence step.
// Grid: 128 blocks (8 h-columns each), 256 threads.
// Lane layout within warp: gi = lane (0..31): gate = gi>>3, hl = gi&7.
// Each thread: 1 gate-column g, 4 batch rows; dot over K=1024 (float4).
// Gate coupling resolved with warp shuffles; lanes of gate 0 write output.
// ----------------------------------------------------------------------------
__device__ __forceinline__ float hsig(float v) {
    return __saturatef(v * 0.16666666666666666f + 0.5f);
}
__device__ __forceinline__ float htanh(float v) {
    return fminf(fmaxf(v, -1.f), 1.f);
}

__global__ __launch_bounds__(256) void lstm_step(const float* __restrict__ R,
                                                 const float* __restrict__ y_prev,
                                                 const float* __restrict__ c_prev,
                                                 float* __restrict__ y_out,
                                                 float* __restrict__ c_out,
                                                 int t)
{
    const int tid  = threadIdx.x;
    const int gi   = tid & 31;        // lane
    const int bg   = tid >> 5;        // 0..7
    const int gate = gi >> 3;         // 0..3
    const int hl   = gi & 7;          // 0..7
    const int h    = blockIdx.x * 8 + hl;
    const int g    = gate * HH + h;
    const int b0   = bg * 4;

    const float4* __restrict__ Rr = (const float4*)(R + (size_t)g * HH);
    const float4* __restrict__ Y  = (const float4*)y_prev;   // [32][256]

    float acc0 = 0.f, acc1 = 0.f, acc2 = 0.f, acc3 = 0.f;
#pragma unroll 4
    for (int k = 0; k < HH / 4; k++) {
        float4 r  = __ldg(&Rr[k]);
        float4 v0 = __ldg(&Y[(b0 + 0) * (HH / 4) + k]);
        float4 v1 = __ldg(&Y[(b0 + 1) * (HH / 4) + k]);
        float4 v2 = __ldg(&Y[(b0 + 2) * (HH / 4) + k]);
        float4 v3 = __ldg(&Y[(b0 + 3) * (HH / 4) + k]);
        acc0 += v0.x * r.x + v0.y * r.y + v0.z * r.z + v0.w * r.w;
        acc1 += v1.x * r.x + v1.y * r.y + v1.z * r.z + v1.w * r.w;
        acc2 += v2.x * r.x + v2.y * r.y + v2.z * r.z + v2.w * r.w;
        acc3 += v3.x * r.x + v3.y * r.y + v3.z * r.z + v3.w * r.w;
    }

    const float* __restrict__ gp = g_gates + (size_t)t * BB * G4;
    float val[4];
    val[0] = acc0 + gp[(size_t)(b0 + 0) * G4 + g];
    val[1] = acc1 + gp[(size_t)(b0 + 1) * G4 + g];
    val[2] = acc2 + gp[(size_t)(b0 + 2) * G4 + g];
    val[3] = acc3 + gp[(size_t)(b0 + 3) * G4 + g];

    const unsigned m = 0xffffffffu;
#pragma unroll
    for (int j = 0; j < 4; j++) {
        float iv = __shfl_sync(m, val[j], hl);
        float fv = __shfl_sync(m, val[j], hl + 8);
        float zv = __shfl_sync(m, val[j], hl + 16);
        float ov = __shfl_sync(m, val[j], hl + 24);
        if (gate == 0) {
            int b   = b0 + j;
            float i_ = hsig(iv);
            float f_ = hsig(fv);
            float z_ = htanh(zv);
            float o_ = hsig(ov);
            float c  = c_prev[(size_t)b * HH + h];
            float cn = f_ * c + i_ * z_;
            float yn = o_ * htanh(cn);
            c_out[(size_t)b * HH + h] = cn;
            y_out[(size_t)b * HH + h] = yn;
        }
    }
}

// ----------------------------------------------------------------------------
// Launch: one GEMM + 512 step kernels (graph-capturable, allocation-free)
// ----------------------------------------------------------------------------
extern "C" void kernel_launch(void* const* d_in, const int* in_sizes, int n_in,
                              void* d_out, int out_size)
{
    const float* y0 = (const float*)d_in[0];
    const float* c0 = (const float*)d_in[1];
    const float* x  = (const float*)d_in[2];
    const float* W  = (const float*)d_in[3];
    const float* R  = (const float*)d_in[4];
    const float* bW = (const float*)d_in[5];
    const float* bR = (const float*)d_in[6];

    float* yout = (float*)d_out;                         // [T][B][H]
    float* cout = yout + (size_t)TT * BB * HH;           // [T][B][H]

    gemm_pre<<<dim3(G4 / 64, (TT * BB) / 128), 256>>>(x, W, bW, bR);

    for (int t = 0; t < TT; t++) {
        const float* yp = t ? (yout + (size_t)(t - 1) * BB * HH) : y0;
        const float* cp = t ? (cout + (size_t)(t - 1) * BB * HH) : c0;
        lstm_step<<<128, 256>>>(R, yp, cp,
                                yout + (size_t)t * BB * HH,
                                cout + (size_t)t * BB * HH, t);
    }
}

// round 2
// speedup vs baseline: 3.4077x; 3.4077x over previous
#include <cuda_runtime.h>

#define TT 512
#define BB 32
#define II 1024
#define HH 1024
#define G4 4096   // 4*H
#define NB 128    // persistent CTAs
#define NTH 512   // threads per CTA

// 256 MB scratch for gates_pre [T][B][4H]
__device__ float g_gates[(size_t)TT * BB * G4];
// double-buffered transposed y: [buf][kc(256)][b(32)] float4, +32 slack float4 for overread
__device__ float4 g_yT[2][256 * 32 + 32];
// grid barrier counter (monotonic within one run; reset by init kernel)
__device__ unsigned g_count;

// ----------------------------------------------------------------------------
// GEMM1: g_gates[m][n] = sum_k x[m][k] * W[n][k] + bW[n] + bR[n]
// ----------------------------------------------------------------------------
__global__ __launch_bounds__(256) void gemm_pre(const float* __restrict__ x,
                                                const float* __restrict__ W,
                                                const float* __restrict__ bW,
                                                const float* __restrict__ bR)
{
    __shared__ float AsT[16][132];
    __shared__ float BsT[16][68];

    const int tid = threadIdx.x;
    const int n0 = blockIdx.x * 64;
    const int m0 = blockIdx.y * 128;
    const int tx = tid & 15;
    const int ty = tid >> 4;

    float acc[8][4];
#pragma unroll
    for (int i = 0; i < 8; i++)
#pragma unroll
        for (int j = 0; j < 4; j++) acc[i][j] = 0.f;

    for (int k0 = 0; k0 < II; k0 += 16) {
#pragma unroll
        for (int q = 0; q < 2; q++) {
            int f   = tid * 2 + q;
            int row = f >> 2;
            int c4  = (f & 3) * 4;
            float4 v = *(const float4*)&x[(size_t)(m0 + row) * II + k0 + c4];
            AsT[c4 + 0][row] = v.x;
            AsT[c4 + 1][row] = v.y;
            AsT[c4 + 2][row] = v.z;
            AsT[c4 + 3][row] = v.w;
        }
        {
            int row = tid >> 2;
            int c4  = (tid & 3) * 4;
            float4 v = *(const float4*)&W[(size_t)(n0 + row) * II + k0 + c4];
            BsT[c4 + 0][row] = v.x;
            BsT[c4 + 1][row] = v.y;
            BsT[c4 + 2][row] = v.z;
            BsT[c4 + 3][row] = v.w;
        }
        __syncthreads();

#pragma unroll
        for (int k = 0; k < 16; k++) {
            float4 a0 = *(const float4*)&AsT[k][ty * 8];
            float4 a1 = *(const float4*)&AsT[k][ty * 8 + 4];
            float4 bv = *(const float4*)&BsT[k][tx * 4];
            float a[8] = {a0.x, a0.y, a0.z, a0.w, a1.x, a1.y, a1.z, a1.w};
            float b[4] = {bv.x, bv.y, bv.z, bv.w};
#pragma unroll
            for (int i = 0; i < 8; i++)
#pragma unroll
                for (int j = 0; j < 4; j++)
                    acc[i][j] += a[i] * b[j];
        }
        __syncthreads();
    }

    float bias[4];
#pragma unroll
    for (int j = 0; j < 4; j++) {
        int n = n0 + tx * 4 + j;
        bias[j] = bW[n] + bR[n];
    }
#pragma unroll
    for (int i = 0; i < 8; i++) {
        int m = m0 + ty * 8 + i;
        float* outp = &g_gates[(size_t)m * G4 + n0 + tx * 4];
#pragma unroll
        for (int j = 0; j < 4; j++)
            outp[j] = acc[i][j] + bias[j];
    }
}

// ----------------------------------------------------------------------------
// Init: reset barrier, transpose y0 [32][1024] -> g_yT[0][k/4][b].w components
// ----------------------------------------------------------------------------
__global__ __launch_bounds__(256) void init_kernel(const float* __restrict__ y0)
{
    int i = blockIdx.x * 256 + threadIdx.x;   // 0..32767
    if (i == 0) g_count = 0;
    int b = i >> 10;
    int k = i & 1023;
    ((float*)&g_yT[0][0])[((k >> 2) * 32 + b) * 4 + (k & 3)] = y0[i];
}

// ----------------------------------------------------------------------------
// Persistent recurrence kernel.
// 128 CTAs, one per SM. CTA blk owns h-slice [blk*8, blk*8+8), all 4 gates
// = 32 R rows held in SMEM for the whole run.
// Warp w (16 warps): gate gq = w&3 (8 rows), k-quarter kq = w>>2 (256 k).
// Lane = batch. Per 4-k chunk: 1 coalesced LDG.128 (yT) + 8 uniform LDS.128
// (R) + 32 FMA.  c state lives in registers of threads 0..255.
// ----------------------------------------------------------------------------
__device__ __forceinline__ float hsig(float v) {
    return __saturatef(v * 0.16666666666666666f + 0.5f);
}
__device__ __forceinline__ float htanh(float v) {
    return fminf(fmaxf(v, -1.f), 1.f);
}

__device__ __forceinline__ void grid_bar(unsigned target) {
    __syncthreads();
    if (threadIdx.x == 0) {
        __threadfence();
        atomicAdd(&g_count, 1u);
        while (*((volatile unsigned*)&g_count) < target) { }
        __threadfence();
    }
    __syncthreads();
}

extern __shared__ float smem_dyn[];   // [0..32767]: R slice [32][1024]; then sm_out[4][32][32]

__global__ __launch_bounds__(NTH, 1) void lstm_persist(const float* __restrict__ R,
                                                       const float* __restrict__ c0,
                                                       float* __restrict__ yout,
                                                       float* __restrict__ cout)
{
    const int tid = threadIdx.x;
    const int blk = blockIdx.x;
    float* Rs = smem_dyn;                       // 32 rows x 1024 floats
    float* sm_out = smem_dyn + 32 * 1024;       // [4][32][32]

    // Load R slice: row rr = g*8 + hl  ->  global row G = g*HH + blk*8 + hl
    {
        float4* Rs4 = (float4*)Rs;
        const float4* R4 = (const float4*)R;
        for (int idx = tid; idx < 32 * 256; idx += NTH) {
            int rr = idx >> 8;
            int kc = idx & 255;
            int g = rr >> 3, hl = rr & 7;
            int G = g * HH + blk * 8 + hl;
            Rs4[idx] = R4[(size_t)G * 256 + kc];
        }
    }
    __syncthreads();

    const int w    = tid >> 5;
    const int lane = tid & 31;
    const int gq   = w & 3;     // gate / row group
    const int kq   = w >> 2;    // k quarter

    // gate-phase identity (threads 0..255)
    const int b  = tid >> 3;
    const int hl = tid & 7;
    const int h  = blk * 8 + hl;

    float c_val = 0.f;
    if (tid < 256) c_val = c0[(size_t)b * HH + h];

    const float4* Rs4 = (const float4*)Rs;

    for (int t = 0; t < TT; t++) {
        // Prefetch gates_pre for this (t, b, h) early (DRAM latency hidden by k-loop)
        float gp0 = 0.f, gp1 = 0.f, gp2 = 0.f, gp3 = 0.f;
        if (tid < 256) {
            const float* gp = g_gates + (size_t)t * BB * G4 + (size_t)b * G4 + h;
            gp0 = gp[0 * HH]; gp1 = gp[1 * HH]; gp2 = gp[2 * HH]; gp3 = gp[3 * HH];
        }

        // k-loop: warp covers kc in [kq*64, kq*64+64)
        const float4* yq = &g_yT[t & 1][(kq * 64) * 32 + lane];
        const float4* rb = Rs4 + (gq * 8) * 256 + kq * 64;

        float acc[8];
#pragma unroll
        for (int r = 0; r < 8; r++) acc[r] = 0.f;

        float4 yc = yq[0];
#pragma unroll 4
        for (int c = 0; c < 64; c++) {
            float4 yn = yq[(c + 1) * 32];   // slack padding makes last read safe
#pragma unroll
            for (int r = 0; r < 8; r++) {
                float4 rv = rb[r * 256 + c];
                acc[r] += yc.x * rv.x + yc.y * rv.y + yc.z * rv.z + yc.w * rv.w;
            }
            yc = yn;
        }

        // stash partials: sm_out[kq][gq*8 + r][lane]
        float* so = sm_out + (kq * 32 + gq * 8) * 32 + lane;
#pragma unroll
        for (int r = 0; r < 8; r++) so[r * 32] = acc[r];
        __syncthreads();

        // gate phase
        if (tid < 256) {
            float si = gp0, sf = gp1, sz = gp2, so4 = gp3;
#pragma unroll
            for (int q = 0; q < 4; q++) {
                const float* base = sm_out + (q * 32) * 32 + b;
                si  += base[(0 * 8 + hl) * 32];
                sf  += base[(1 * 8 + hl) * 32];
                sz  += base[(2 * 8 + hl) * 32];
                so4 += base[(3 * 8 + hl) * 32];
            }
            float i_ = hsig(si);
            float f_ = hsig(sf);
            float z_ = htanh(sz);
            float o_ = hsig(so4);
            c_val = f_ * c_val + i_ * z_;
            float y_ = o_ * htanh(c_val);

            size_t oidx = (size_t)t * BB * HH + (size_t)b * HH + h;
            yout[oidx] = y_;
            cout[oidx] = c_val;
            // transposed y for next step
            ((float*)&g_yT[(t + 1) & 1][0])[((h >> 2) * 32 + b) * 4 + (h & 3)] = y_;
        }

        if (t < TT - 1) grid_bar((unsigned)(NB * (t + 1)));
    }
}

// ----------------------------------------------------------------------------
extern "C" void kernel_launch(void* const* d_in, const int* in_sizes, int n_in,
                              void* d_out, int out_size)
{
    const float* y0 = (const float*)d_in[0];
    const float* c0 = (const float*)d_in[1];
    const float* x  = (const float*)d_in[2];
    const float* W  = (const float*)d_in[3];
    const float* R  = (const float*)d_in[4];
    const float* bW = (const float*)d_in[5];
    const float* bR = (const float*)d_in[6];

    float* yout = (float*)d_out;
    float* cout = yout + (size_t)TT * BB * HH;

    const int smem_bytes = 32 * 1024 * 4 + 4 * 32 * 32 * 4;   // 147456
    cudaFuncSetAttribute(lstm_persist, cudaFuncAttributeMaxDynamicSharedMemorySize, smem_bytes);

    init_kernel<<<128, 256>>>(y0);
    gemm_pre<<<dim3(G4 / 64, (TT * BB) / 128), 256>>>(x, W, bW, bR);
    lstm_persist<<<NB, NTH, smem_bytes>>>(R, c0, yout, cout);
}

// round 4
// speedup vs baseline: 4.2749x; 1.2545x over previous
#include <cuda_runtime.h>
#include <cuda_bf16.h>
#include <cstdint>

#define TT 512
#define BB 32
#define II 1024
#define HH 1024
#define G4 4096   // 4*H
#define NB 128    // persistent CTAs
#define NTH 512   // threads per CTA

#define KCH 48          // K' chunks of 64 (3*1024/64)
#define MT  128         // M tiles (16384/128)
#define NTB 32          // N tiles (4096/128)
#define GT_A 16384      // 128 rows * 128 B
#define GT_B 16384
#define GSTAGE_B (GT_A + GT_B)   // 32768
#define GSTG 3

// ------------------------- device scratch -------------------------
__device__ float g_gates[(size_t)TT * BB * G4];                 // 256 MB
__device__ unsigned char g_At[(size_t)KCH * MT * GT_A];         // 96 MB pre-tiled, pre-swizzled
__device__ unsigned char g_Bt[(size_t)KCH * NTB * GT_B];        // 24 MB
__device__ float4 g_yT[2][256 * 32 + 32];
__device__ unsigned g_count;

// ------------------------- helpers -------------------------
__device__ __forceinline__ uint32_t smem_u32(const void* p) {
    uint32_t a;
    asm("{ .reg .u64 t; cvta.to.shared.u64 t, %1; cvt.u32.u64 %0, t; }" : "=r"(a) : "l"(p));
    return a;
}
__device__ __forceinline__ void ldsm4(uint32_t (&r)[4], uint32_t addr) {
    asm volatile("ldmatrix.sync.aligned.m8n8.x4.shared.b16 {%0,%1,%2,%3}, [%4];"
        : "=r"(r[0]), "=r"(r[1]), "=r"(r[2]), "=r"(r[3]) : "r"(addr));
}
__device__ __forceinline__ void mma16816(float (&d)[4], const uint32_t (&a)[4],
                                         uint32_t b0, uint32_t b1) {
    asm volatile("mma.sync.aligned.m16n8k16.row.col.f32.bf16.bf16.f32 "
        "{%0,%1,%2,%3}, {%4,%5,%6,%7}, {%8,%9}, {%0,%1,%2,%3};"
        : "+f"(d[0]), "+f"(d[1]), "+f"(d[2]), "+f"(d[3])
        : "r"(a[0]), "r"(a[1]), "r"(a[2]), "r"(a[3]), "r"(b0), "r"(b1));
}
__device__ __forceinline__ void cp16(uint32_t sdst, const void* gsrc) {
    asm volatile("cp.async.cg.shared.global [%0], [%1], 16;" :: "r"(sdst), "l"(gsrc) : "memory");
}
__device__ __forceinline__ void cp_commit() {
    asm volatile("cp.async.commit_group;" ::: "memory");
}
template<int N> __device__ __forceinline__ void cp_wait() {
    asm volatile("cp.async.wait_group %0;" :: "n"(N) : "memory");
}
__device__ __forceinline__ uint32_t pack_bf2(float a, float b) {
    __nv_bfloat162 h = __floats2bfloat162_rn(a, b);
    return *(uint32_t*)&h;
}

// ------------------------------------------------------------------
// Conversion: x -> A' = [hi | hi | lo]; tiles [kch][mt] of 128x64 bf16,
// SW128-swizzled 128B rows.
// ------------------------------------------------------------------
__global__ __launch_bounds__(256) void convA(const float* __restrict__ x)
{
    int t = blockIdx.x * 256 + threadIdx.x;
    int cg = t & 7;
    int kc = (t >> 3) & 15;
    int m  = t >> 7;

    const float4* xp = (const float4*)(x + (size_t)m * II + kc * 64 + cg * 8);
    float4 v0 = xp[0], v1 = xp[1];
    float f[8] = {v0.x, v0.y, v0.z, v0.w, v1.x, v1.y, v1.z, v1.w};
    float hif[8], lof[8];
#pragma unroll
    for (int i = 0; i < 8; i++) {
        __nv_bfloat16 h = __float2bfloat16_rn(f[i]);
        hif[i] = __bfloat162float(h);
        lof[i] = f[i] - hif[i];
    }
    uint4 hi4 = {pack_bf2(hif[0], hif[1]), pack_bf2(hif[2], hif[3]),
                 pack_bf2(hif[4], hif[5]), pack_bf2(hif[6], hif[7])};
    uint4 lo4 = {pack_bf2(lof[0], lof[1]), pack_bf2(lof[2], lof[3]),
                 pack_bf2(lof[4], lof[5]), pack_bf2(lof[6], lof[7])};

    int mt = m >> 7, r = m & 127;
    uint32_t off = (uint32_t)r * 128 + cg * 16;
    uint32_t sw  = off ^ ((off >> 3) & 0x70);

    *(uint4*)(g_At + ((size_t)(kc +  0) * MT + mt) * GT_A + sw) = hi4;
    *(uint4*)(g_At + ((size_t)(kc + 16) * MT + mt) * GT_A + sw) = hi4;
    *(uint4*)(g_At + ((size_t)(kc + 32) * MT + mt) * GT_A + sw) = lo4;
}

// W -> B' = [hi | lo | hi]; tiles [kch][nt] of 128x64 bf16
__global__ __launch_bounds__(256) void convB(const float* __restrict__ W)
{
    int t = blockIdx.x * 256 + threadIdx.x;
    int cg = t & 7;
    int kc = (t >> 3) & 15;
    int n  = t >> 7;

    const float4* wp = (const float4*)(W + (size_t)n * II + kc * 64 + cg * 8);
    float4 v0 = wp[0], v1 = wp[1];
    float f[8] = {v0.x, v0.y, v0.z, v0.w, v1.x, v1.y, v1.z, v1.w};
    float hif[8], lof[8];
#pragma unroll
    for (int i = 0; i < 8; i++) {
        __nv_bfloat16 h = __float2bfloat16_rn(f[i]);
        hif[i] = __bfloat162float(h);
        lof[i] = f[i] - hif[i];
    }
    uint4 hi4 = {pack_bf2(hif[0], hif[1]), pack_bf2(hif[2], hif[3]),
                 pack_bf2(hif[4], hif[5]), pack_bf2(hif[6], hif[7])};
    uint4 lo4 = {pack_bf2(lof[0], lof[1]), pack_bf2(lof[2], lof[3]),
                 pack_bf2(lof[4], lof[5]), pack_bf2(lof[6], lof[7])};

    int nt = n >> 7, r = n & 127;
    uint32_t off = (uint32_t)r * 128 + cg * 16;
    uint32_t sw  = off ^ ((off >> 3) & 0x70);

    *(uint4*)(g_Bt + ((size_t)(kc +  0) * NTB + nt) * GT_B + sw) = hi4;
    *(uint4*)(g_Bt + ((size_t)(kc + 16) * NTB + nt) * GT_B + sw) = lo4;
    *(uint4*)(g_Bt + ((size_t)(kc + 32) * NTB + nt) * GT_B + sw) = hi4;
}

// ------------------------------------------------------------------
// HMMA GEMM: g_gates[m][n] = A'[m]·B'[n] + bW[n] + bR[n]
// CTA 128x128, BK=64 bf16, 3-stage cp.async pipeline, 8 warps (32x64 each).
// ------------------------------------------------------------------
__device__ __forceinline__ void load_stage(uint32_t sbase, int s, int c, int mt, int nt, int tid)
{
    uint32_t smA = sbase + s * GSTAGE_B;
    uint32_t smB = smA + GT_A;
    const unsigned char* gA = g_At + ((size_t)c * MT + mt) * GT_A;
    const unsigned char* gB = g_Bt + ((size_t)c * NTB + nt) * GT_B;
#pragma unroll
    for (int i = 0; i < 4; i++) {
        uint32_t off = (uint32_t)(tid + i * 256) * 16;
        cp16(smA + off, gA + off);
    }
#pragma unroll
    for (int i = 0; i < 4; i++) {
        uint32_t off = (uint32_t)(tid + i * 256) * 16;
        cp16(smB + off, gB + off);
    }
}

__global__ __launch_bounds__(256, 1) void gemm_mma(const float* __restrict__ bW,
                                                   const float* __restrict__ bR)
{
    extern __shared__ __align__(128) unsigned char smg[];
    const uint32_t sbase = smem_u32(smg);

    const int tid  = threadIdx.x;
    const int lane = tid & 31;
    const int warp = tid >> 5;
    const int wm   = warp & 3;        // m quarter
    const int wn   = warp >> 2;       // n half
    const int mt   = blockIdx.x;
    const int nt   = blockIdx.y;

    float acc[2][8][4];
#pragma unroll
    for (int i = 0; i < 2; i++)
#pragma unroll
        for (int j = 0; j < 8; j++)
#pragma unroll
            for (int q = 0; q < 4; q++) acc[i][j][q] = 0.f;

    load_stage(sbase, 0, 0, mt, nt, tid); cp_commit();
    load_stage(sbase, 1, 1, mt, nt, tid); cp_commit();

    const int rl = lane & 15;
    const int chalf = lane >> 4;

#pragma unroll 1
    for (int c = 0; c < KCH; c++) {
        if (c + 2 < KCH) load_stage(sbase, (c + 2) % GSTG, c + 2, mt, nt, tid);
        cp_commit();
        cp_wait<2>();
        __syncthreads();

        const uint32_t smA = sbase + (c % GSTG) * GSTAGE_B;
        const uint32_t smB = smA + GT_A;

#pragma unroll
        for (int ks = 0; ks < 4; ks++) {
            const int kb = ks * 32 + chalf * 16;
            uint32_t a[2][4];
#pragma unroll
            for (int i = 0; i < 2; i++) {
                uint32_t off = (uint32_t)(wm * 32 + i * 16 + rl) * 128 + kb;
                ldsm4(a[i], smA + (off ^ ((off >> 3) & 0x70)));
            }
            uint32_t b[4][4];
#pragma unroll
            for (int j = 0; j < 4; j++) {
                uint32_t off = (uint32_t)(wn * 64 + j * 16 + rl) * 128 + kb;
                ldsm4(b[j], smB + (off ^ ((off >> 3) & 0x70)));
            }
#pragma unroll
            for (int i = 0; i < 2; i++)
#pragma unroll
                for (int j = 0; j < 4; j++) {
                    mma16816(acc[i][2 * j + 0], a[i], b[j][0], b[j][2]);
                    mma16816(acc[i][2 * j + 1], a[i], b[j][1], b[j][3]);
                }
        }
        __syncthreads();
    }

    // epilogue
    const int m0  = mt * 128 + wm * 32 + (lane >> 2);
    const int n0g = nt * 128 + wn * 64;
#pragma unroll
    for (int i = 0; i < 2; i++) {
#pragma unroll
        for (int j = 0; j < 8; j++) {
            int n = n0g + j * 8 + (lane & 3) * 2;
            float bx = bW[n] + bR[n];
            float by = bW[n + 1] + bR[n + 1];
            int r0 = m0 + i * 16;
            float2 o0 = {acc[i][j][0] + bx, acc[i][j][1] + by};
            float2 o1 = {acc[i][j][2] + bx, acc[i][j][3] + by};
            *(float2*)&g_gates[(size_t)r0 * G4 + n] = o0;
            *(float2*)&g_gates[(size_t)(r0 + 8) * G4 + n] = o1;
        }
    }
}

// ------------------------------------------------------------------
// Init: reset barrier, transpose y0 into g_yT[0]
// ------------------------------------------------------------------
__global__ __launch_bounds__(256) void init_kernel(const float* __restrict__ y0)
{
    int i = blockIdx.x * 256 + threadIdx.x;
    if (i == 0) g_count = 0;
    int b = i >> 10;
    int k = i & 1023;
    ((float*)&g_yT[0][0])[((k >> 2) * 32 + b) * 4 + (k & 3)] = y0[i];
}

// ------------------------------------------------------------------
// Persistent recurrence (unchanged from R2)
// ------------------------------------------------------------------
__device__ __forceinline__ float hsig(float v) {
    return __saturatef(v * 0.16666666666666666f + 0.5f);
}
__device__ __forceinline__ float htanh(float v) {
    return fminf(fmaxf(v, -1.f), 1.f);
}
__device__ __forceinline__ void grid_bar(unsigned target) {
    __syncthreads();
    if (threadIdx.x == 0) {
        __threadfence();
        atomicAdd(&g_count, 1u);
        while (*((volatile unsigned*)&g_count) < target) { }
        __threadfence();
    }
    __syncthreads();
}

extern __shared__ float smem_dyn[];

__global__ __launch_bounds__(NTH, 1) void lstm_persist(const float* __restrict__ R,
                                                       const float* __restrict__ c0,
                                                       float* __restrict__ yout,
                                                       float* __restrict__ cout)
{
    const int tid = threadIdx.x;
    const int blk = blockIdx.x;
    float* Rs = smem_dyn;
    float* sm_out = smem_dyn + 32 * 1024;

    {
        float4* Rs4 = (float4*)Rs;
        const float4* R4 = (const float4*)R;
        for (int idx = tid; idx < 32 * 256; idx += NTH) {
            int rr = idx >> 8;
            int kc = idx & 255;
            int g = rr >> 3, hl = rr & 7;
            int G = g * HH + blk * 8 + hl;
            Rs4[idx] = R4[(size_t)G * 256 + kc];
        }
    }
    __syncthreads();

    const int w    = tid >> 5;
    const int lane = tid & 31;
    const int gq   = w & 3;
    const int kq   = w >> 2;

    const int b  = tid >> 3;
    const int hl = tid & 7;
    const int h  = blk * 8 + hl;

    float c_val = 0.f;
    if (tid < 256) c_val = c0[(size_t)b * HH + h];

    const float4* Rs4 = (const float4*)Rs;

    for (int t = 0; t < TT; t++) {
        float gp0 = 0.f, gp1 = 0.f, gp2 = 0.f, gp3 = 0.f;
        if (tid < 256) {
            const float* gp = g_gates + (size_t)t * BB * G4 + (size_t)b * G4 + h;
            gp0 = gp[0 * HH]; gp1 = gp[1 * HH]; gp2 = gp[2 * HH]; gp3 = gp[3 * HH];
        }

        const float4* yq = &g_yT[t & 1][(kq * 64) * 32 + lane];
        const float4* rb = Rs4 + (gq * 8) * 256 + kq * 64;

        float acc[8];
#pragma unroll
        for (int r = 0; r < 8; r++) acc[r] = 0.f;

        float4 yc = yq[0];
#pragma unroll 4
        for (int c = 0; c < 64; c++) {
            float4 yn = yq[(c + 1) * 32];
#pragma unroll
            for (int r = 0; r < 8; r++) {
                float4 rv = rb[r * 256 + c];
                acc[r] += yc.x * rv.x + yc.y * rv.y + yc.z * rv.z + yc.w * rv.w;
            }
            yc = yn;
        }

        float* so = sm_out + (kq * 32 + gq * 8) * 32 + lane;
#pragma unroll
        for (int r = 0; r < 8; r++) so[r * 32] = acc[r];
        __syncthreads();

        if (tid < 256) {
            float si = gp0, sf = gp1, sz = gp2, so4 = gp3;
#pragma unroll
            for (int q = 0; q < 4; q++) {
                const float* base = sm_out + (q * 32) * 32 + b;
                si  += base[(0 * 8 + hl) * 32];
                sf  += base[(1 * 8 + hl) * 32];
                sz  += base[(2 * 8 + hl) * 32];
                so4 += base[(3 * 8 + hl) * 32];
            }
            float i_ = hsig(si);
            float f_ = hsig(sf);
            float z_ = htanh(sz);
            float o_ = hsig(so4);
            c_val = f_ * c_val + i_ * z_;
            float y_ = o_ * htanh(c_val);

            size_t oidx = (size_t)t * BB * HH + (size_t)b * HH + h;
            yout[oidx] = y_;
            cout[oidx] = c_val;
            ((float*)&g_yT[(t + 1) & 1][0])[((h >> 2) * 32 + b) * 4 + (h & 3)] = y_;
        }

        if (t < TT - 1) grid_bar((unsigned)(NB * (t + 1)));
    }
}

// ------------------------------------------------------------------
extern "C" void kernel_launch(void* const* d_in, const int* in_sizes, int n_in,
                              void* d_out, int out_size)
{
    const float* y0 = (const float*)d_in[0];
    const float* c0 = (const float*)d_in[1];
    const float* x  = (const float*)d_in[2];
    const float* W  = (const float*)d_in[3];
    const float* R  = (const float*)d_in[4];
    const float* bW = (const float*)d_in[5];
    const float* bR = (const float*)d_in[6];

    float* yout = (float*)d_out;
    float* cout = yout + (size_t)TT * BB * HH;

    const int smem_gemm = GSTG * GSTAGE_B;                     // 98304
    const int smem_rec  = 32 * 1024 * 4 + 4 * 32 * 32 * 4;     // 147456
    cudaFuncSetAttribute(gemm_mma, cudaFuncAttributeMaxDynamicSharedMemorySize, smem_gemm);
    cudaFuncSetAttribute(lstm_persist, cudaFuncAttributeMaxDynamicSharedMemorySize, smem_rec);

    convA<<<8192, 256>>>(x);
    convB<<<2048, 256>>>(W);
    init_kernel<<<128, 256>>>(y0);
    gemm_mma<<<dim3(MT, NTB), 256, smem_gemm>>>(bW, bR);
    lstm_persist<<<NB, NTH, smem_rec>>>(R, c0, yout, cout);
}

// round 5
// speedup vs baseline: 9.1446x; 2.1392x over previous
#include <cuda_runtime.h>
#include <cuda_bf16.h>
#include <cstdint>

#define TT 512
#define BB 32
#define II 1024
#define HH 1024
#define G4 4096   // 4*H
#define NB 128    // persistent CTAs
#define NTH 256   // threads per CTA (recurrence)

#define KCH 48          // K' chunks of 64 (3*1024/64)
#define MT  128         // M tiles (16384/128)
#define NTB 32          // N tiles (4096/128)
#define GT_A 16384
#define GT_B 16384
#define GSTAGE_B (GT_A + GT_B)
#define GSTG 3

// recurrence smem offsets (bytes)
#define RS_H 0
#define RS_L 65536
#define YSM  131072                 // [2 buf][ hi 16K | lo 16K ]
#define REDO 196608                 // red [8][4][32] floats = 4KB
#define GSMO 200704                 // gsm [32][33] floats = 4224B
#define SMEM_REC (GSMO + 32 * 33 * 4)

// ------------------------- device scratch -------------------------
__device__ float g_gates[(size_t)TT * BB * G4];                 // 256 MB
__device__ unsigned char g_At[(size_t)KCH * MT * GT_A];
__device__ unsigned char g_Bt[(size_t)KCH * NTB * GT_B];
__device__ __nv_bfloat16 g_yh[2][BB * HH];   // y hi, [buf][b][k]
__device__ __nv_bfloat16 g_yl[2][BB * HH];   // y lo
__device__ unsigned g_count;

// ------------------------- helpers -------------------------
__device__ __forceinline__ uint32_t smem_u32(const void* p) {
    uint32_t a;
    asm("{ .reg .u64 t; cvta.to.shared.u64 t, %1; cvt.u32.u64 %0, t; }" : "=r"(a) : "l"(p));
    return a;
}
__device__ __forceinline__ void ldsm4(uint32_t (&r)[4], uint32_t addr) {
    asm volatile("ldmatrix.sync.aligned.m8n8.x4.shared.b16 {%0,%1,%2,%3}, [%4];"
        : "=r"(r[0]), "=r"(r[1]), "=r"(r[2]), "=r"(r[3]) : "r"(addr));
}
__device__ __forceinline__ void mma16816(float (&d)[4], const uint32_t (&a)[4],
                                         uint32_t b0, uint32_t b1) {
    asm volatile("mma.sync.aligned.m16n8k16.row.col.f32.bf16.bf16.f32 "
        "{%0,%1,%2,%3}, {%4,%5,%6,%7}, {%8,%9}, {%0,%1,%2,%3};"
        : "+f"(d[0]), "+f"(d[1]), "+f"(d[2]), "+f"(d[3])
        : "r"(a[0]), "r"(a[1]), "r"(a[2]), "r"(a[3]), "r"(b0), "r"(b1));
}
__device__ __forceinline__ void cp16(uint32_t sdst, const void* gsrc) {
    asm volatile("cp.async.cg.shared.global [%0], [%1], 16;" :: "r"(sdst), "l"(gsrc) : "memory");
}
__device__ __forceinline__ void cp_commit() {
    asm volatile("cp.async.commit_group;" ::: "memory");
}
template<int N> __device__ __forceinline__ void cp_wait() {
    asm volatile("cp.async.wait_group %0;" :: "n"(N) : "memory");
}
__device__ __forceinline__ uint32_t pack_bf2(float a, float b) {
    __nv_bfloat162 h = __floats2bfloat162_rn(a, b);
    return *(uint32_t*)&h;
}
__device__ __forceinline__ float hsig(float v) {
    return __saturatef(v * 0.16666666666666666f + 0.5f);
}
__device__ __forceinline__ float htanh(float v) {
    return fminf(fmaxf(v, -1.f), 1.f);
}

// ------------------------------------------------------------------
// Conversion kernels (unchanged from R4)
// ------------------------------------------------------------------
__global__ __launch_bounds__(256) void convA(const float* __restrict__ x)
{
    int t = blockIdx.x * 256 + threadIdx.x;
    int cg = t & 7;
    int kc = (t >> 3) & 15;
    int m  = t >> 7;

    const float4* xp = (const float4*)(x + (size_t)m * II + kc * 64 + cg * 8);
    float4 v0 = xp[0], v1 = xp[1];
    float f[8] = {v0.x, v0.y, v0.z, v0.w, v1.x, v1.y, v1.z, v1.w};
    float hif[8], lof[8];
#pragma unroll
    for (int i = 0; i < 8; i++) {
        __nv_bfloat16 h = __float2bfloat16_rn(f[i]);
        hif[i] = __bfloat162float(h);
        lof[i] = f[i] - hif[i];
    }
    uint4 hi4 = {pack_bf2(hif[0], hif[1]), pack_bf2(hif[2], hif[3]),
                 pack_bf2(hif[4], hif[5]), pack_bf2(hif[6], hif[7])};
    uint4 lo4 = {pack_bf2(lof[0], lof[1]), pack_bf2(lof[2], lof[3]),
                 pack_bf2(lof[4], lof[5]), pack_bf2(lof[6], lof[7])};

    int mt = m >> 7, r = m & 127;
    uint32_t off = (uint32_t)r * 128 + cg * 16;
    uint32_t sw  = off ^ ((off >> 3) & 0x70);

    *(uint4*)(g_At + ((size_t)(kc +  0) * MT + mt) * GT_A + sw) = hi4;
    *(uint4*)(g_At + ((size_t)(kc + 16) * MT + mt) * GT_A + sw) = hi4;
    *(uint4*)(g_At + ((size_t)(kc + 32) * MT + mt) * GT_A + sw) = lo4;
}

__global__ __launch_bounds__(256) void convB(const float* __restrict__ W)
{
    int t = blockIdx.x * 256 + threadIdx.x;
    int cg = t & 7;
    int kc = (t >> 3) & 15;
    int n  = t >> 7;

    const float4* wp = (const float4*)(W + (size_t)n * II + kc * 64 + cg * 8);
    float4 v0 = wp[0], v1 = wp[1];
    float f[8] = {v0.x, v0.y, v0.z, v0.w, v1.x, v1.y, v1.z, v1.w};
    float hif[8], lof[8];
#pragma unroll
    for (int i = 0; i < 8; i++) {
        __nv_bfloat16 h = __float2bfloat16_rn(f[i]);
        hif[i] = __bfloat162float(h);
        lof[i] = f[i] - hif[i];
    }
    uint4 hi4 = {pack_bf2(hif[0], hif[1]), pack_bf2(hif[2], hif[3]),
                 pack_bf2(hif[4], hif[5]), pack_bf2(hif[6], hif[7])};
    uint4 lo4 = {pack_bf2(lof[0], lof[1]), pack_bf2(lof[2], lof[3]),
                 pack_bf2(lof[4], lof[5]), pack_bf2(lof[6], lof[7])};

    int nt = n >> 7, r = n & 127;
    uint32_t off = (uint32_t)r * 128 + cg * 16;
    uint32_t sw  = off ^ ((off >> 3) & 0x70);

    *(uint4*)(g_Bt + ((size_t)(kc +  0) * NTB + nt) * GT_B + sw) = hi4;
    *(uint4*)(g_Bt + ((size_t)(kc + 16) * NTB + nt) * GT_B + sw) = lo4;
    *(uint4*)(g_Bt + ((size_t)(kc + 32) * NTB + nt) * GT_B + sw) = hi4;
}

// ------------------------------------------------------------------
// HMMA pre-GEMM (unchanged from R4)
// ------------------------------------------------------------------
__device__ __forceinline__ void load_stage(uint32_t sbase, int s, int c, int mt, int nt, int tid)
{
    uint32_t smA = sbase + s * GSTAGE_B;
    uint32_t smB = smA + GT_A;
    const unsigned char* gA = g_At + ((size_t)c * MT + mt) * GT_A;
    const unsigned char* gB = g_Bt + ((size_t)c * NTB + nt) * GT_B;
#pragma unroll
    for (int i = 0; i < 4; i++) {
        uint32_t off = (uint32_t)(tid + i * 256) * 16;
        cp16(smA + off, gA + off);
    }
#pragma unroll
    for (int i = 0; i < 4; i++) {
        uint32_t off = (uint32_t)(tid + i * 256) * 16;
        cp16(smB + off, gB + off);
    }
}

__global__ __launch_bounds__(256, 1) void gemm_mma(const float* __restrict__ bW,
                                                   const float* __restrict__ bR)
{
    extern __shared__ __align__(128) unsigned char smg[];
    const uint32_t sbase = smem_u32(smg);

    const int tid  = threadIdx.x;
    const int lane = tid & 31;
    const int warp = tid >> 5;
    const int wm   = warp & 3;
    const int wn   = warp >> 2;
    const int mt   = blockIdx.x;
    const int nt   = blockIdx.y;

    float acc[2][8][4];
#pragma unroll
    for (int i = 0; i < 2; i++)
#pragma unroll
        for (int j = 0; j < 8; j++)
#pragma unroll
            for (int q = 0; q < 4; q++) acc[i][j][q] = 0.f;

    load_stage(sbase, 0, 0, mt, nt, tid); cp_commit();
    load_stage(sbase, 1, 1, mt, nt, tid); cp_commit();

    const int rl = lane & 15;
    const int chalf = lane >> 4;

#pragma unroll 1
    for (int c = 0; c < KCH; c++) {
        if (c + 2 < KCH) load_stage(sbase, (c + 2) % GSTG, c + 2, mt, nt, tid);
        cp_commit();
        cp_wait<2>();
        __syncthreads();

        const uint32_t smA = sbase + (c % GSTG) * GSTAGE_B;
        const uint32_t smB = smA + GT_A;

#pragma unroll
        for (int ks = 0; ks < 4; ks++) {
            const int kb = ks * 32 + chalf * 16;
            uint32_t a[2][4];
#pragma unroll
            for (int i = 0; i < 2; i++) {
                uint32_t off = (uint32_t)(wm * 32 + i * 16 + rl) * 128 + kb;
                ldsm4(a[i], smA + (off ^ ((off >> 3) & 0x70)));
            }
            uint32_t b[4][4];
#pragma unroll
            for (int j = 0; j < 4; j++) {
                uint32_t off = (uint32_t)(wn * 64 + j * 16 + rl) * 128 + kb;
                ldsm4(b[j], smB + (off ^ ((off >> 3) & 0x70)));
            }
#pragma unroll
            for (int i = 0; i < 2; i++)
#pragma unroll
                for (int j = 0; j < 4; j++) {
                    mma16816(acc[i][2 * j + 0], a[i], b[j][0], b[j][2]);
                    mma16816(acc[i][2 * j + 1], a[i], b[j][1], b[j][3]);
                }
        }
        __syncthreads();
    }

    const int m0  = mt * 128 + wm * 32 + (lane >> 2);
    const int n0g = nt * 128 + wn * 64;
#pragma unroll
    for (int i = 0; i < 2; i++) {
#pragma unroll
        for (int j = 0; j < 8; j++) {
            int n = n0g + j * 8 + (lane & 3) * 2;
            float bx = bW[n] + bR[n];
            float by = bW[n + 1] + bR[n + 1];
            int r0 = m0 + i * 16;
            float2 o0 = {acc[i][j][0] + bx, acc[i][j][1] + by};
            float2 o1 = {acc[i][j][2] + bx, acc[i][j][3] + by};
            *(float2*)&g_gates[(size_t)r0 * G4 + n] = o0;
            *(float2*)&g_gates[(size_t)(r0 + 8) * G4 + n] = o1;
        }
    }
}

// ------------------------------------------------------------------
// Init: reset barrier; y0 -> bf16 hi/lo buffers (layout [b][k], no transpose)
// ------------------------------------------------------------------
__global__ __launch_bounds__(256) void init_kernel(const float* __restrict__ y0)
{
    int i = blockIdx.x * 256 + threadIdx.x;   // 0..32767
    if (i == 0) g_count = 0;
    float v = y0[i];
    __nv_bfloat16 h = __float2bfloat16_rn(v);
    g_yh[0][i] = h;
    g_yl[0][i] = __float2bfloat16_rn(v - __bfloat162float(h));
}

// ------------------------------------------------------------------
// Persistent tensor-core recurrence.
// CTA blk owns 32 gate-rows of R (n = g*8+hl -> R row g*1024+blk*8+hl),
// held in SMEM as bf16 hi/lo, swizzled for ldmatrix.
// 8 warps: wm=warp&1 (batch half), wn=(warp>>1)&1 (n half), wk=warp>>2 (k parity).
// ------------------------------------------------------------------
__device__ __forceinline__ void grid_bar(unsigned target) {
    __syncthreads();
    if (threadIdx.x == 0) {
        __threadfence();
        atomicAdd(&g_count, 1u);
        while (*((volatile unsigned*)&g_count) < target) { }
        __threadfence();
    }
    __syncthreads();
}

extern __shared__ __align__(128) unsigned char smrec[];

__global__ __launch_bounds__(NTH, 1) void lstm_persist(const float* __restrict__ R,
                                                       const float* __restrict__ c0,
                                                       float* __restrict__ yout,
                                                       float* __restrict__ cout)
{
    const int tid = threadIdx.x;
    const int blk = blockIdx.x;
    const uint32_t sbase = smem_u32(smrec);

    // ---- load + split + swizzle R slice into SMEM (once) ----
    for (int i = tid; i < 4096; i += NTH) {        // 32 rows x 128 granules(8 bf16)
        int rr  = i >> 7;
        int g16 = i & 127;
        int G   = (rr >> 3) * HH + blk * 8 + (rr & 7);
        const float4* p = (const float4*)(R + (size_t)G * HH + g16 * 8);
        float4 v0 = p[0], v1 = p[1];
        float f[8] = {v0.x, v0.y, v0.z, v0.w, v1.x, v1.y, v1.z, v1.w};
        float hif[8], lof[8];
#pragma unroll
        for (int j = 0; j < 8; j++) {
            __nv_bfloat16 h = __float2bfloat16_rn(f[j]);
            hif[j] = __bfloat162float(h);
            lof[j] = f[j] - hif[j];
        }
        uint4 hi4 = {pack_bf2(hif[0], hif[1]), pack_bf2(hif[2], hif[3]),
                     pack_bf2(hif[4], hif[5]), pack_bf2(hif[6], hif[7])};
        uint4 lo4 = {pack_bf2(lof[0], lof[1]), pack_bf2(lof[2], lof[3]),
                     pack_bf2(lof[4], lof[5]), pack_bf2(lof[6], lof[7])};
        uint32_t off = (uint32_t)rr * 2048 + (((uint32_t)g16 * 16) ^ (((uint32_t)rr & 7) << 4));
        *(uint4*)(smrec + RS_H + off) = hi4;
        *(uint4*)(smrec + RS_L + off) = lo4;
    }
    __syncthreads();

    const int lane  = tid & 31;
    const int warp  = tid >> 5;
    const int wm    = warp & 1;
    const int wn    = (warp >> 1) & 1;
    const int wk    = warp >> 2;
    const int rl    = lane & 15;
    const int chalf = lane >> 4;

    // epilogue identity
    const int b  = tid >> 3;
    const int hl = tid & 7;
    const int h  = blk * 8 + hl;

    float c_val = c0[(size_t)b * HH + h];

    float* red = (float*)(smrec + REDO);           // [8 j][4 w][32 lane]
    float* gsm = (float*)(smrec + GSMO);           // [32 n][33]

    // A-row addresses (constant across steps): row = wm*16 + rl
    const uint32_t arow = (uint32_t)(wm * 16 + rl);
    const uint32_t nrow = (uint32_t)(wn * 16 + rl);
    const uint32_t aswz = (arow & 7) << 4;
    const uint32_t nswz = (nrow & 7) << 4;
    const uint32_t abase = sbase + YSM + arow * 512;
    const uint32_t rbase_h = sbase + RS_H + nrow * 2048;
    const uint32_t rbase_l = sbase + RS_L + nrow * 2048;

    for (int t = 0; t < TT; t++) {
        const int rbuf = t & 1;
        const __nv_bfloat16* yhg = g_yh[rbuf];
        const __nv_bfloat16* ylg = g_yl[rbuf];

        // prefetch gates_pre
        const float* gp = g_gates + (size_t)t * BB * G4 + (size_t)b * G4 + h;
        float gp0 = gp[0 * HH], gp1 = gp[1 * HH], gp2 = gp[2 * HH], gp3 = gp[3 * HH];

        float acc0[4] = {0.f, 0.f, 0.f, 0.f};
        float acc1[4] = {0.f, 0.f, 0.f, 0.f};

        // ---- issue chunk 0 ----
#pragma unroll
        for (int i = 0; i < 8; i++) {
            int gran = tid + i * 256;              // 0..2047
            int half = gran >> 10;
            int bb   = (gran >> 5) & 31;
            int gi   = gran & 31;
            const __nv_bfloat16* src = (half ? ylg : yhg) + bb * 1024 + 0 * 256 + gi * 8;
            uint32_t dst = sbase + YSM + 0 * 32768 + half * 16384 + bb * 512
                         + (((uint32_t)gi * 16) ^ (((uint32_t)bb & 7) << 4));
            cp16(dst, src);
        }
        cp_commit();

#pragma unroll 1
        for (int c = 0; c < 4; c++) {
            if (c + 1 < 4) {
#pragma unroll
                for (int i = 0; i < 8; i++) {
                    int gran = tid + i * 256;
                    int half = gran >> 10;
                    int bb   = (gran >> 5) & 31;
                    int gi   = gran & 31;
                    const __nv_bfloat16* src = (half ? ylg : yhg) + bb * 1024 + (c + 1) * 256 + gi * 8;
                    uint32_t dst = sbase + YSM + ((c + 1) & 1) * 32768 + half * 16384 + bb * 512
                                 + (((uint32_t)gi * 16) ^ (((uint32_t)bb & 7) << 4));
                    cp16(dst, src);
                }
                cp_commit();
                cp_wait<1>();
            } else {
                cp_wait<0>();
            }
            __syncthreads();

            const uint32_t ybh = sbase + YSM + (c & 1) * 32768 + arow * 512;
            const uint32_t ybl = ybh + 16384;
            const uint32_t kcb = (uint32_t)c * 512;

#pragma unroll
            for (int s2 = 0; s2 < 8; s2++) {
                const int s = s2 * 2 + wk;
                const uint32_t aoff = (uint32_t)(s * 32 + chalf * 16);
                const uint32_t koff = kcb + aoff;
                uint32_t ah[4], al[4], bh[4], bl[4];
                ldsm4(ah, ybh - arow * 512 + arow * 512 + (aoff ^ aswz));
                ldsm4(bh, rbase_h + (koff ^ nswz));
                ldsm4(bl, rbase_l + (koff ^ nswz));
                ldsm4(al, ybl + (aoff ^ aswz));
                mma16816(acc0, ah, bh[0], bh[2]);
                mma16816(acc1, ah, bh[1], bh[3]);
                mma16816(acc0, ah, bl[0], bl[2]);
                mma16816(acc1, ah, bl[1], bl[3]);
                mma16816(acc0, al, bh[0], bh[2]);
                mma16816(acc1, al, bh[1], bh[3]);
            }
            __syncthreads();
        }

        // ---- k-split reduce ----
        if (wk == 1) {
            const int w4 = warp & 3;
#pragma unroll
            for (int j = 0; j < 4; j++) {
                red[((j)     * 4 + w4) * 32 + lane] = acc0[j];
                red[((j + 4) * 4 + w4) * 32 + lane] = acc1[j];
            }
        }
        __syncthreads();
        if (wk == 0) {
            const int w4 = warp & 3;
#pragma unroll
            for (int j = 0; j < 4; j++) {
                acc0[j] += red[((j)     * 4 + w4) * 32 + lane];
                acc1[j] += red[((j + 4) * 4 + w4) * 32 + lane];
            }
            // write gsm[n][m] (stride 33)
            const int mrow = wm * 16 + (lane >> 2);
            const int nb0  = wn * 16 + (lane & 3) * 2;
            gsm[(nb0 + 0) * 33 + mrow] = acc0[0];
            gsm[(nb0 + 1) * 33 + mrow] = acc0[1];
            gsm[(nb0 + 0) * 33 + mrow + 8] = acc0[2];
            gsm[(nb0 + 1) * 33 + mrow + 8] = acc0[3];
            gsm[(nb0 + 8) * 33 + mrow] = acc1[0];
            gsm[(nb0 + 9) * 33 + mrow] = acc1[1];
            gsm[(nb0 + 8) * 33 + mrow + 8] = acc1[2];
            gsm[(nb0 + 9) * 33 + mrow + 8] = acc1[3];
        }
        __syncthreads();

        // ---- gate epilogue (all 256 threads) ----
        {
            float si  = gp0 + gsm[(0 * 8 + hl) * 33 + b];
            float sf  = gp1 + gsm[(1 * 8 + hl) * 33 + b];
            float sz  = gp2 + gsm[(2 * 8 + hl) * 33 + b];
            float so4 = gp3 + gsm[(3 * 8 + hl) * 33 + b];
            float i_ = hsig(si);
            float f_ = hsig(sf);
            float z_ = htanh(sz);
            float o_ = hsig(so4);
            c_val = f_ * c_val + i_ * z_;
            float y_ = o_ * htanh(c_val);

            size_t oidx = (size_t)t * BB * HH + (size_t)b * HH + h;
            yout[oidx] = y_;
            cout[oidx] = c_val;

            __nv_bfloat16 yh = __float2bfloat16_rn(y_);
            g_yh[(t + 1) & 1][b * HH + h] = yh;
            g_yl[(t + 1) & 1][b * HH + h] = __float2bfloat16_rn(y_ - __bfloat162float(yh));
        }

        if (t < TT - 1) grid_bar((unsigned)(NB * (t + 1)));
    }
}

// ------------------------------------------------------------------
extern "C" void kernel_launch(void* const* d_in, const int* in_sizes, int n_in,
                              void* d_out, int out_size)
{
    const float* y0 = (const float*)d_in[0];
    const float* c0 = (const float*)d_in[1];
    const float* x  = (const float*)d_in[2];
    const float* W  = (const float*)d_in[3];
    const float* R  = (const float*)d_in[4];
    const float* bW = (const float*)d_in[5];
    const float* bR = (const float*)d_in[6];

    float* yout = (float*)d_out;
    float* cout = yout + (size_t)TT * BB * HH;

    const int smem_gemm = GSTG * GSTAGE_B;     // 98304
    cudaFuncSetAttribute(gemm_mma, cudaFuncAttributeMaxDynamicSharedMemorySize, smem_gemm);
    cudaFuncSetAttribute(lstm_persist, cudaFuncAttributeMaxDynamicSharedMemorySize, SMEM_REC);

    convA<<<8192, 256>>>(x);
    convB<<<2048, 256>>>(W);
    init_kernel<<<128, 256>>>(y0);
    gemm_mma<<<dim3(MT, NTB), 256, smem_gemm>>>(bW, bR);
    lstm_persist<<<NB, NTH, SMEM_REC>>>(R, c0, yout, cout);
}